// round 11
// baseline (speedup 1.0000x reference)
#include <cuda_runtime.h>
#include <math.h>

#define BB 32
#define GG 20
#define NC 80
#define AT 8400   // 6400 + 1600 + 400

// ---------------- device scratch (static globals; no runtime allocation) ----
__device__ float g_bbox[BB*AT*4];
__device__ float g_obj[BB*AT];
__device__ float g_suml1p[BB*AT];
__device__ float g_delta[BB*GG*AT];   // (lp - l1p) at gt class of g
__device__ float g_cost[BB*GG*AT];
__device__ float g_iou[BB*GG*AT];     // masked ious (ious_m)
__device__ unsigned int  g_inboth[BB*AT];   // bitmask over g
__device__ unsigned char g_fgc[BB*AT];      // fg_cand
__device__ unsigned char g_match[BB*GG*AT];
__device__ double g_acc[4];           // iou, obj, cls, num_fg

__device__ __forceinline__ void anchor_meta(int a, int &lvl, int &loc,
                                            float &gx, float &gy, float &s) {
    if (a < 6400)      { lvl = 0; loc = a;        gx = (float)(loc % 80); gy = (float)(loc / 80); s = 8.f;  }
    else if (a < 8000) { lvl = 1; loc = a - 6400; gx = (float)(loc % 40); gy = (float)(loc / 40); s = 16.f; }
    else               { lvl = 2; loc = a - 8000; gx = (float)(loc % 20); gy = (float)(loc / 20); s = 32.f; }
}

__device__ __forceinline__ float bce(float x, float t) {
    return fmaxf(x, 0.f) - x * t + log1pf(expf(-fabsf(x)));
}

// ---------------- kernel 0: zero accumulators ------------------------------
__global__ void k_zero() {
    if (threadIdx.x < 4) g_acc[threadIdx.x] = 0.0;
}

// ---------------- kernel 1: decode + per-anchor class stats + fg_cand ------
__global__ void k_decode(const float* __restrict__ p8, const float* __restrict__ p16,
                         const float* __restrict__ p32, const float* __restrict__ lab) {
    int b = blockIdx.y;
    int a = blockIdx.x * blockDim.x + threadIdx.x;

    __shared__ unsigned int s_mask[NC];     // class -> bitmask of gt indices
    __shared__ float s_box[GG][4];
    for (int i = threadIdx.x; i < NC; i += blockDim.x) s_mask[i] = 0u;
    __syncthreads();
    if (threadIdx.x < GG) {
        const float* L = lab + (b * GG + threadIdx.x) * 5;
        s_box[threadIdx.x][0] = L[0]; s_box[threadIdx.x][1] = L[1];
        s_box[threadIdx.x][2] = L[2]; s_box[threadIdx.x][3] = L[3];
        int c = (int)L[4];
        if (c >= 0 && c < NC) atomicOr(&s_mask[c], 1u << threadIdx.x);
    }
    __syncthreads();
    if (a >= AT) return;

    int lvl, loc; float gx, gy, s;
    anchor_meta(a, lvl, loc, gx, gy, s);
    const float* p; int HW;
    if (lvl == 0)      { p = p8;  HW = 6400; }
    else if (lvl == 1) { p = p16; HW = 1600; }
    else               { p = p32; HW = 400;  }
    const float* base = p + (size_t)b * 85 * HW + loc;

    float tx = base[0];
    float ty = base[(size_t)HW];
    float tw = base[2 * (size_t)HW];
    float th = base[3 * (size_t)HW];
    float to = base[4 * (size_t)HW];

    float bx = (tx + gx) * s, by = (ty + gy) * s;
    float bw = expf(tw) * s,  bh = expf(th) * s;

    int ba = b * AT + a;
    g_bbox[ba * 4 + 0] = bx; g_bbox[ba * 4 + 1] = by;
    g_bbox[ba * 4 + 2] = bw; g_bbox[ba * 4 + 3] = bh;
    g_obj[ba] = to;

    float sobj = 1.f / (1.f + expf(-to));
    float suml1p = 0.f;
    for (int c = 0; c < NC; c++) {
        float x  = base[(size_t)(5 + c) * HW];
        float sc = 1.f / (1.f + expf(-x));
        float pc = sqrtf(sc * sobj);
        float lp = fmaxf(logf(pc), -100.f);
        float l1 = fmaxf(log1pf(-pc), -100.f);
        suml1p += l1;
        unsigned m = s_mask[c];
        float v = lp - l1;
        while (m) {
            int g = __ffs((int)m) - 1;
            m &= m - 1;
            g_delta[((size_t)b * GG + g) * AT + a] = v;
        }
    }
    g_suml1p[ba] = suml1p;

    // fg_cand + in_both bitmask
    float xc = (gx + 0.5f) * s, yc = (gy + 0.5f) * s;
    float r = 2.5f * s;
    unsigned mb = 0u; bool fg = false;
    #pragma unroll
    for (int g = 0; g < GG; g++) {
        float cx = s_box[g][0], cy = s_box[g][1], w = s_box[g][2], h = s_box[g][3];
        bool inbox = (xc > cx - 0.5f * w) && (xc < cx + 0.5f * w) &&
                     (yc > cy - 0.5f * h) && (yc < cy + 0.5f * h);
        bool inctr = (xc > cx - r) && (xc < cx + r) &&
                     (yc > cy - r) && (yc < cy + r);
        fg = fg || inbox || inctr;
        if (inbox && inctr) mb |= (1u << g);
    }
    g_fgc[ba] = fg ? 1 : 0;
    g_inboth[ba] = mb;
}

// ---------------- kernel 2: cost + iou matrix -------------------------------
__global__ void k_cost(const float* __restrict__ lab) {
    int b = blockIdx.z, g = blockIdx.y;
    int a = blockIdx.x * blockDim.x + threadIdx.x;
    __shared__ float box[4];
    if (threadIdx.x < 4) box[threadIdx.x] = lab[(b * GG + g) * 5 + threadIdx.x];
    __syncthreads();
    if (a >= AT) return;

    int ba = b * AT + a;
    float bx = g_bbox[ba * 4 + 0], by = g_bbox[ba * 4 + 1];
    float bw = g_bbox[ba * 4 + 2], bh = g_bbox[ba * 4 + 3];
    float cx = box[0], cy = box[1], w = box[2], h = box[3];

    float gt_tlx = cx - 0.5f * w, gt_tly = cy - 0.5f * h;
    float gt_brx = cx + 0.5f * w, gt_bry = cy + 0.5f * h;
    float pr_tlx = bx - 0.5f * bw, pr_tly = by - 0.5f * bh;
    float pr_brx = bx + 0.5f * bw, pr_bry = by + 0.5f * bh;
    float tlx = fmaxf(gt_tlx, pr_tlx), tly = fmaxf(gt_tly, pr_tly);
    float brx = fminf(gt_brx, pr_brx), bry = fminf(gt_bry, pr_bry);
    float inter = ((tlx < brx) && (tly < bry)) ? (brx - tlx) * (bry - tly) : 0.f;
    float iou = inter / (w * h + bw * bh - inter + 1e-16f);

    bool fg = g_fgc[ba] != 0;
    float ioum = fg ? iou : 0.f;
    size_t idx = ((size_t)b * GG + g) * AT + a;
    float cls_cost = -(g_delta[idx] + g_suml1p[ba]);
    float iou_cost = -logf(ioum + 1e-8f);
    bool inboth = (g_inboth[ba] >> g) & 1u;
    float cost = cls_cost + 3.f * iou_cost + (inboth ? 0.f : 100000.f) + (fg ? 0.f : 1e9f);
    g_cost[idx] = cost;
    g_iou[idx]  = ioum;
}

// ---------------- kernel 3: per-(b,g) dyn_k selection ------------------------
__global__ void k_select() {
    const int NT = 256;
    int g = blockIdx.x, b = blockIdx.y;
    int tid = threadIdx.x;
    size_t row = ((size_t)b * GG + g) * AT;
    const float* irow = g_iou + row;
    const float* crow = g_cost + row;
    unsigned char* mrow = g_match + row;

    for (int a = tid; a < AT; a += NT) mrow[a] = 0;

    // ---- phase 1: sum of top-10 largest masked ious -> dyn_k ----
    float top[10];
    #pragma unroll
    for (int i = 0; i < 10; i++) top[i] = -1.f;
    for (int a = tid; a < AT; a += NT) {
        float v = irow[a];
        if (v > top[9]) {
            int i = 9;
            for (; i > 0 && v > top[i - 1]; i--) top[i] = top[i - 1];
            top[i] = v;
        }
    }
    __shared__ float sv[NT];
    __shared__ int   si[NT];
    float sum = 0.f; int ptr = 0;
    for (int r = 0; r < 10; r++) {
        sv[tid] = (ptr < 10) ? top[ptr] : -1e30f;
        si[tid] = tid;
        __syncthreads();
        for (int off = NT / 2; off > 0; off >>= 1) {
            if (tid < off) {
                if (sv[tid + off] > sv[tid] ||
                    (sv[tid + off] == sv[tid] && si[tid + off] < si[tid])) {
                    sv[tid] = sv[tid + off]; si[tid] = si[tid + off];
                }
            }
            __syncthreads();
        }
        float wv = sv[0]; int wt = si[0];
        __syncthreads();
        if (tid == wt) ptr++;
        sum += wv;       // descending order, matches top_k().sum()
    }
    int dynk = (int)sum;            // truncation toward zero (sum >= 0)
    dynk = max(1, min(dynk, 10));

    // ---- phase 2: dyn_k smallest costs, tie-break by anchor index ----
    float cv[10]; int ci[10];
    #pragma unroll
    for (int i = 0; i < 10; i++) { cv[i] = 3.4e38f; ci[i] = 0x7fffffff; }
    for (int a = tid; a < AT; a += NT) {
        float v = crow[a];
        if (v < cv[9] || (v == cv[9] && a < ci[9])) {
            int i = 9;
            for (; i > 0 && (v < cv[i - 1] || (v == cv[i - 1] && a < ci[i - 1])); i--) {
                cv[i] = cv[i - 1]; ci[i] = ci[i - 1];
            }
            cv[i] = v; ci[i] = a;
        }
    }
    int p2 = 0;
    for (int r = 0; r < dynk; r++) {
        sv[tid] = (p2 < 10) ? cv[p2] : 3.4e38f;
        si[tid] = (p2 < 10) ? ci[p2] : 0x7fffffff;
        __syncthreads();
        for (int off = NT / 2; off > 0; off >>= 1) {
            if (tid < off) {
                float ov = sv[tid + off]; int oi = si[tid + off];
                if (ov < sv[tid] || (ov == sv[tid] && oi < si[tid])) {
                    sv[tid] = ov; si[tid] = oi;
                }
            }
            __syncthreads();
        }
        int wi = si[0];
        __syncthreads();
        if (p2 < 10 && ci[p2] == wi) p2++;
        if (tid == 0 && wi < AT && g_fgc[b * AT + wi]) mrow[wi] = 1;
    }
}

// ---------------- kernel 4: resolve multi-matches + losses ------------------
__global__ void k_loss(const float* __restrict__ p8, const float* __restrict__ p16,
                       const float* __restrict__ p32, const float* __restrict__ lab) {
    int b = blockIdx.y;
    int a = blockIdx.x * blockDim.x + threadIdx.x;
    double l_iou = 0.0, l_obj = 0.0, l_cls = 0.0, nfg = 0.0;

    if (a < AT) {
        int ba = b * AT + a;
        int cnt = 0, first = -1;
        #pragma unroll
        for (int g = 0; g < GG; g++) {
            if (g_match[((size_t)b * GG + g) * AT + a]) { cnt++; if (first < 0) first = g; }
        }
        int matched = first;
        if (cnt > 1) {   // multi: reassign to global argmin over g (first min)
            float best = 3.4e38f; int bi = 0;
            #pragma unroll
            for (int g = 0; g < GG; g++) {
                float c = g_cost[((size_t)b * GG + g) * AT + a];
                if (c < best) { best = c; bi = g; }
            }
            matched = bi;
        }
        bool fg = cnt > 0;
        l_obj = (double)bce(g_obj[ba], fg ? 1.f : 0.f);
        if (fg) {
            nfg = 1.0;
            float pred_iou = g_iou[((size_t)b * GG + matched) * AT + a];
            const float* L = lab + (b * GG + matched) * 5;
            float gcx = L[0], gcy = L[1], gw = L[2], gh = L[3];
            int mc = (int)L[4];
            float bx = g_bbox[ba * 4 + 0], by = g_bbox[ba * 4 + 1];
            float bw = g_bbox[ba * 4 + 2], bh = g_bbox[ba * 4 + 3];
            // GIoU loss
            float b_tlx = bx - 0.5f * bw, b_tly = by - 0.5f * bh;
            float b_brx = bx + 0.5f * bw, b_bry = by + 0.5f * bh;
            float t_tlx = gcx - 0.5f * gw, t_tly = gcy - 0.5f * gh;
            float t_brx = gcx + 0.5f * gw, t_bry = gcy + 0.5f * gh;
            float tlx = fmaxf(b_tlx, t_tlx), tly = fmaxf(b_tly, t_tly);
            float brx = fminf(b_brx, t_brx), bry = fminf(b_bry, t_bry);
            float inter = ((tlx < brx) && (tly < bry)) ? (brx - tlx) * (bry - tly) : 0.f;
            float uni = bw * bh + gw * gh - inter;
            float iou = inter / (uni + 1e-16f);
            float ctlx = fminf(b_tlx, t_tlx), ctly = fminf(b_tly, t_tly);
            float cbrx = fmaxf(b_brx, t_brx), cbry = fmaxf(b_bry, t_bry);
            float areac = fmaxf((cbrx - ctlx) * (cbry - ctly), 1e-16f);
            float giou = iou - (areac - uni) / areac;
            giou = fminf(fmaxf(giou, -1.f), 1.f);
            l_iou = (double)(1.f - giou);
            // classification BCE (only fg contributes)
            int lvl, loc; float gx, gy, s;
            anchor_meta(a, lvl, loc, gx, gy, s);
            const float* p; int HW;
            if (lvl == 0)      { p = p8;  HW = 6400; }
            else if (lvl == 1) { p = p16; HW = 1600; }
            else               { p = p32; HW = 400;  }
            const float* base = p + (size_t)b * 85 * HW + loc;
            float cls_sum = 0.f;
            for (int c = 0; c < NC; c++) {
                float x = base[(size_t)(5 + c) * HW];
                float t = (c == mc) ? pred_iou : 0.f;
                cls_sum += bce(x, t);
            }
            l_cls = (double)cls_sum;
        }
    }

    __shared__ double sd[256];
    double vals[4] = { l_iou, l_obj, l_cls, nfg };
    for (int k = 0; k < 4; k++) {
        sd[threadIdx.x] = vals[k];
        __syncthreads();
        for (int off = 128; off > 0; off >>= 1) {
            if (threadIdx.x < off) sd[threadIdx.x] += sd[threadIdx.x + off];
            __syncthreads();
        }
        if (threadIdx.x == 0) atomicAdd(&g_acc[k], sd[0]);
        __syncthreads();
    }
}

// ---------------- kernel 5: finalize -----------------------------------------
__global__ void k_final(float* out) {
    double nf = g_acc[3];
    if (nf < 1.0) nf = 1.0;
    out[0] = (float)((5.0 * g_acc[0] + g_acc[1] + g_acc[2]) / nf);
}

// ---------------- launch ------------------------------------------------------
extern "C" void kernel_launch(void* const* d_in, const int* in_sizes, int n_in,
                              void* d_out, int out_size) {
    // Identify inputs by element count for robustness.
    const float *p8 = nullptr, *p16 = nullptr, *p32 = nullptr, *lab = nullptr;
    for (int i = 0; i < n_in; i++) {
        const float* ptr = (const float*)d_in[i];
        switch (in_sizes[i]) {
            case 32 * 85 * 80 * 80: p8  = ptr; break;
            case 32 * 85 * 40 * 40: p16 = ptr; break;
            case 32 * 85 * 20 * 20: p32 = ptr; break;
            case 32 * 20 * 5:       lab = ptr; break;
            default: break;
        }
    }
    if (!p8 || !p16 || !p32 || !lab) {   // fall back to metadata order
        p8 = (const float*)d_in[0]; p16 = (const float*)d_in[1];
        p32 = (const float*)d_in[2]; lab = (const float*)d_in[3];
    }

    dim3 blk(256);
    dim3 gA((AT + 255) / 256, BB);
    k_zero<<<1, 32>>>();
    k_decode<<<gA, blk>>>(p8, p16, p32, lab);
    k_cost<<<dim3((AT + 255) / 256, GG, BB), blk>>>(lab);
    k_select<<<dim3(GG, BB), 256>>>();
    k_loss<<<gA, blk>>>(p8, p16, p32, lab);
    k_final<<<1, 1>>>((float*)d_out);
}

// round 12
// speedup vs baseline: 1.0078x; 1.0078x over previous
#include <cuda_runtime.h>
#include <math.h>

#define BB 32
#define GG 20
#define NC 80
#define AT 8400   // 6400 + 1600 + 400

// ---------------- device scratch (static globals; no runtime allocation) ----
__device__ float g_bbox[BB*AT*4];
__device__ float g_obj[BB*AT];
__device__ float g_suml1p[BB*AT];
__device__ float g_delta[BB*GG*AT];   // (lp - l1p) at gt class of g
__device__ float g_cost[BB*GG*AT];
__device__ float g_iou[BB*GG*AT];     // masked ious (ious_m)
__device__ unsigned int  g_inboth[BB*AT];   // bitmask over g
__device__ unsigned char g_fgc[BB*AT];      // fg_cand
__device__ unsigned char g_match[BB*GG*AT];
__device__ double g_acc[4];           // iou, obj, cls, num_fg

__device__ __forceinline__ void anchor_meta(int a, int &lvl, int &loc,
                                            float &gx, float &gy, float &s) {
    if (a < 6400)      { lvl = 0; loc = a;        gx = (float)(loc % 80); gy = (float)(loc / 80); s = 8.f;  }
    else if (a < 8000) { lvl = 1; loc = a - 6400; gx = (float)(loc % 40); gy = (float)(loc / 40); s = 16.f; }
    else               { lvl = 2; loc = a - 8000; gx = (float)(loc % 20); gy = (float)(loc / 20); s = 32.f; }
}

__device__ __forceinline__ float bce(float x, float t) {
    return fmaxf(x, 0.f) - x * t + log1pf(expf(-fabsf(x)));
}

// ---------------- kernel 0: zero accumulators ------------------------------
__global__ void k_zero() {
    if (threadIdx.x < 4) g_acc[threadIdx.x] = 0.0;
}

// ---------------- kernel 1: decode + per-anchor class stats + fg_cand ------
__global__ void k_decode(const float* __restrict__ p8, const float* __restrict__ p16,
                         const float* __restrict__ p32, const float* __restrict__ lab) {
    int b = blockIdx.y;
    int a = blockIdx.x * blockDim.x + threadIdx.x;

    __shared__ unsigned int s_mask[NC];     // class -> bitmask of gt indices
    __shared__ float s_box[GG][4];
    for (int i = threadIdx.x; i < NC; i += blockDim.x) s_mask[i] = 0u;
    __syncthreads();
    if (threadIdx.x < GG) {
        const float* L = lab + (b * GG + threadIdx.x) * 5;
        s_box[threadIdx.x][0] = L[0]; s_box[threadIdx.x][1] = L[1];
        s_box[threadIdx.x][2] = L[2]; s_box[threadIdx.x][3] = L[3];
        int c = (int)L[4];
        if (c >= 0 && c < NC) atomicOr(&s_mask[c], 1u << threadIdx.x);
    }
    __syncthreads();
    if (a >= AT) return;

    int lvl, loc; float gx, gy, s;
    anchor_meta(a, lvl, loc, gx, gy, s);
    const float* p; int HW;
    if (lvl == 0)      { p = p8;  HW = 6400; }
    else if (lvl == 1) { p = p16; HW = 1600; }
    else               { p = p32; HW = 400;  }
    const float* base = p + (size_t)b * 85 * HW + loc;

    float tx = base[0];
    float ty = base[(size_t)HW];
    float tw = base[2 * (size_t)HW];
    float th = base[3 * (size_t)HW];
    float to = base[4 * (size_t)HW];

    float bx = (tx + gx) * s, by = (ty + gy) * s;
    float bw = expf(tw) * s,  bh = expf(th) * s;

    int ba = b * AT + a;
    g_bbox[ba * 4 + 0] = bx; g_bbox[ba * 4 + 1] = by;
    g_bbox[ba * 4 + 2] = bw; g_bbox[ba * 4 + 3] = bh;
    g_obj[ba] = to;

    float sobj = 1.f / (1.f + expf(-to));
    float suml1p = 0.f;
    for (int c = 0; c < NC; c++) {
        float x  = base[(size_t)(5 + c) * HW];
        float sc = 1.f / (1.f + expf(-x));
        float pc = sqrtf(sc * sobj);
        float lp = fmaxf(logf(pc), -100.f);
        float l1 = fmaxf(log1pf(-pc), -100.f);
        suml1p += l1;
        unsigned m = s_mask[c];
        float v = lp - l1;
        while (m) {
            int g = __ffs((int)m) - 1;
            m &= m - 1;
            g_delta[((size_t)b * GG + g) * AT + a] = v;
        }
    }
    g_suml1p[ba] = suml1p;

    // fg_cand + in_both bitmask
    float xc = (gx + 0.5f) * s, yc = (gy + 0.5f) * s;
    float r = 2.5f * s;
    unsigned mb = 0u; bool fg = false;
    #pragma unroll
    for (int g = 0; g < GG; g++) {
        float cx = s_box[g][0], cy = s_box[g][1], w = s_box[g][2], h = s_box[g][3];
        bool inbox = (xc > cx - 0.5f * w) && (xc < cx + 0.5f * w) &&
                     (yc > cy - 0.5f * h) && (yc < cy + 0.5f * h);
        bool inctr = (xc > cx - r) && (xc < cx + r) &&
                     (yc > cy - r) && (yc < cy + r);
        fg = fg || inbox || inctr;
        if (inbox && inctr) mb |= (1u << g);
    }
    g_fgc[ba] = fg ? 1 : 0;
    g_inboth[ba] = mb;
}

// ---------------- kernel 2: cost + iou matrix -------------------------------
__global__ void k_cost(const float* __restrict__ lab) {
    int b = blockIdx.z, g = blockIdx.y;
    int a = blockIdx.x * blockDim.x + threadIdx.x;
    __shared__ float box[4];
    if (threadIdx.x < 4) box[threadIdx.x] = lab[(b * GG + g) * 5 + threadIdx.x];
    __syncthreads();
    if (a >= AT) return;

    int ba = b * AT + a;
    float bx = g_bbox[ba * 4 + 0], by = g_bbox[ba * 4 + 1];
    float bw = g_bbox[ba * 4 + 2], bh = g_bbox[ba * 4 + 3];
    float cx = box[0], cy = box[1], w = box[2], h = box[3];

    float gt_tlx = cx - 0.5f * w, gt_tly = cy - 0.5f * h;
    float gt_brx = cx + 0.5f * w, gt_bry = cy + 0.5f * h;
    float pr_tlx = bx - 0.5f * bw, pr_tly = by - 0.5f * bh;
    float pr_brx = bx + 0.5f * bw, pr_bry = by + 0.5f * bh;
    float tlx = fmaxf(gt_tlx, pr_tlx), tly = fmaxf(gt_tly, pr_tly);
    float brx = fminf(gt_brx, pr_brx), bry = fminf(gt_bry, pr_bry);
    float inter = ((tlx < brx) && (tly < bry)) ? (brx - tlx) * (bry - tly) : 0.f;
    float iou = inter / (w * h + bw * bh - inter + 1e-16f);

    bool fg = g_fgc[ba] != 0;
    float ioum = fg ? iou : 0.f;
    size_t idx = ((size_t)b * GG + g) * AT + a;
    float cls_cost = -(g_delta[idx] + g_suml1p[ba]);
    float iou_cost = -logf(ioum + 1e-8f);
    bool inboth = (g_inboth[ba] >> g) & 1u;
    float cost = cls_cost + 3.f * iou_cost + (inboth ? 0.f : 100000.f) + (fg ? 0.f : 1e9f);
    g_cost[idx] = cost;
    g_iou[idx]  = ioum;
}

// ---------------- kernel 3: per-(b,g) dyn_k selection ------------------------
__global__ void k_select() {
    const int NT = 256;
    int g = blockIdx.x, b = blockIdx.y;
    int tid = threadIdx.x;
    size_t row = ((size_t)b * GG + g) * AT;
    const float* irow = g_iou + row;
    const float* crow = g_cost + row;
    unsigned char* mrow = g_match + row;

    for (int a = tid; a < AT; a += NT) mrow[a] = 0;

    // ---- phase 1: sum of top-10 largest masked ious -> dyn_k ----
    float top[10];
    #pragma unroll
    for (int i = 0; i < 10; i++) top[i] = -1.f;
    for (int a = tid; a < AT; a += NT) {
        float v = irow[a];
        if (v > top[9]) {
            int i = 9;
            for (; i > 0 && v > top[i - 1]; i--) top[i] = top[i - 1];
            top[i] = v;
        }
    }
    __shared__ float sv[NT];
    __shared__ int   si[NT];
    float sum = 0.f; int ptr = 0;
    for (int r = 0; r < 10; r++) {
        sv[tid] = (ptr < 10) ? top[ptr] : -1e30f;
        si[tid] = tid;
        __syncthreads();
        for (int off = NT / 2; off > 0; off >>= 1) {
            if (tid < off) {
                if (sv[tid + off] > sv[tid] ||
                    (sv[tid + off] == sv[tid] && si[tid + off] < si[tid])) {
                    sv[tid] = sv[tid + off]; si[tid] = si[tid + off];
                }
            }
            __syncthreads();
        }
        float wv = sv[0]; int wt = si[0];
        __syncthreads();
        if (tid == wt) ptr++;
        sum += wv;       // descending order, matches top_k().sum()
    }
    int dynk = (int)sum;            // truncation toward zero (sum >= 0)
    dynk = max(1, min(dynk, 10));

    // ---- phase 2: dyn_k smallest costs, tie-break by anchor index ----
    float cv[10]; int ci[10];
    #pragma unroll
    for (int i = 0; i < 10; i++) { cv[i] = 3.4e38f; ci[i] = 0x7fffffff; }
    for (int a = tid; a < AT; a += NT) {
        float v = crow[a];
        if (v < cv[9] || (v == cv[9] && a < ci[9])) {
            int i = 9;
            for (; i > 0 && (v < cv[i - 1] || (v == cv[i - 1] && a < ci[i - 1])); i--) {
                cv[i] = cv[i - 1]; ci[i] = ci[i - 1];
            }
            cv[i] = v; ci[i] = a;
        }
    }
    int p2 = 0;
    for (int r = 0; r < dynk; r++) {
        sv[tid] = (p2 < 10) ? cv[p2] : 3.4e38f;
        si[tid] = (p2 < 10) ? ci[p2] : 0x7fffffff;
        __syncthreads();
        for (int off = NT / 2; off > 0; off >>= 1) {
            if (tid < off) {
                float ov = sv[tid + off]; int oi = si[tid + off];
                if (ov < sv[tid] || (ov == sv[tid] && oi < si[tid])) {
                    sv[tid] = ov; si[tid] = oi;
                }
            }
            __syncthreads();
        }
        int wi = si[0];
        __syncthreads();
        if (p2 < 10 && ci[p2] == wi) p2++;
        if (tid == 0 && wi < AT && g_fgc[b * AT + wi]) mrow[wi] = 1;
    }
}

// ---------------- kernel 4: resolve multi-matches + losses ------------------
__global__ void k_loss(const float* __restrict__ p8, const float* __restrict__ p16,
                       const float* __restrict__ p32, const float* __restrict__ lab) {
    int b = blockIdx.y;
    int a = blockIdx.x * blockDim.x + threadIdx.x;
    double l_iou = 0.0, l_obj = 0.0, l_cls = 0.0, nfg = 0.0;

    if (a < AT) {
        int ba = b * AT + a;
        int cnt = 0, first = -1;
        #pragma unroll
        for (int g = 0; g < GG; g++) {
            if (g_match[((size_t)b * GG + g) * AT + a]) { cnt++; if (first < 0) first = g; }
        }
        int matched = first;
        if (cnt > 1) {   // multi: reassign to global argmin over g (first min)
            float best = 3.4e38f; int bi = 0;
            #pragma unroll
            for (int g = 0; g < GG; g++) {
                float c = g_cost[((size_t)b * GG + g) * AT + a];
                if (c < best) { best = c; bi = g; }
            }
            matched = bi;
        }
        bool fg = cnt > 0;
        l_obj = (double)bce(g_obj[ba], fg ? 1.f : 0.f);
        if (fg) {
            nfg = 1.0;
            float pred_iou = g_iou[((size_t)b * GG + matched) * AT + a];
            const float* L = lab + (b * GG + matched) * 5;
            float gcx = L[0], gcy = L[1], gw = L[2], gh = L[3];
            int mc = (int)L[4];
            float bx = g_bbox[ba * 4 + 0], by = g_bbox[ba * 4 + 1];
            float bw = g_bbox[ba * 4 + 2], bh = g_bbox[ba * 4 + 3];
            // GIoU loss
            float b_tlx = bx - 0.5f * bw, b_tly = by - 0.5f * bh;
            float b_brx = bx + 0.5f * bw, b_bry = by + 0.5f * bh;
            float t_tlx = gcx - 0.5f * gw, t_tly = gcy - 0.5f * gh;
            float t_brx = gcx + 0.5f * gw, t_bry = gcy + 0.5f * gh;
            float tlx = fmaxf(b_tlx, t_tlx), tly = fmaxf(b_tly, t_tly);
            float brx = fminf(b_brx, t_brx), bry = fminf(b_bry, t_bry);
            float inter = ((tlx < brx) && (tly < bry)) ? (brx - tlx) * (bry - tly) : 0.f;
            float uni = bw * bh + gw * gh - inter;
            float iou = inter / (uni + 1e-16f);
            float ctlx = fminf(b_tlx, t_tlx), ctly = fminf(b_tly, t_tly);
            float cbrx = fmaxf(b_brx, t_brx), cbry = fmaxf(b_bry, t_bry);
            float areac = fmaxf((cbrx - ctlx) * (cbry - ctly), 1e-16f);
            float giou = iou - (areac - uni) / areac;
            giou = fminf(fmaxf(giou, -1.f), 1.f);
            l_iou = (double)(1.f - giou);
            // classification BCE (only fg contributes)
            int lvl, loc; float gx, gy, s;
            anchor_meta(a, lvl, loc, gx, gy, s);
            const float* p; int HW;
            if (lvl == 0)      { p = p8;  HW = 6400; }
            else if (lvl == 1) { p = p16; HW = 1600; }
            else               { p = p32; HW = 400;  }
            const float* base = p + (size_t)b * 85 * HW + loc;
            float cls_sum = 0.f;
            for (int c = 0; c < NC; c++) {
                float x = base[(size_t)(5 + c) * HW];
                float t = (c == mc) ? pred_iou : 0.f;
                cls_sum += bce(x, t);
            }
            l_cls = (double)cls_sum;
        }
    }

    __shared__ double sd[256];
    double vals[4] = { l_iou, l_obj, l_cls, nfg };
    for (int k = 0; k < 4; k++) {
        sd[threadIdx.x] = vals[k];
        __syncthreads();
        for (int off = 128; off > 0; off >>= 1) {
            if (threadIdx.x < off) sd[threadIdx.x] += sd[threadIdx.x + off];
            __syncthreads();
        }
        if (threadIdx.x == 0) atomicAdd(&g_acc[k], sd[0]);
        __syncthreads();
    }
}

// ---------------- kernel 5: finalize -----------------------------------------
__global__ void k_final(float* out) {
    double nf = g_acc[3];
    if (nf < 1.0) nf = 1.0;
    out[0] = (float)((5.0 * g_acc[0] + g_acc[1] + g_acc[2]) / nf);
}

// ---------------- launch ------------------------------------------------------
extern "C" void kernel_launch(void* const* d_in, const int* in_sizes, int n_in,
                              void* d_out, int out_size) {
    // Identify inputs by element count for robustness.
    const float *p8 = nullptr, *p16 = nullptr, *p32 = nullptr, *lab = nullptr;
    for (int i = 0; i < n_in; i++) {
        const float* ptr = (const float*)d_in[i];
        switch (in_sizes[i]) {
            case 32 * 85 * 80 * 80: p8  = ptr; break;
            case 32 * 85 * 40 * 40: p16 = ptr; break;
            case 32 * 85 * 20 * 20: p32 = ptr; break;
            case 32 * 20 * 5:       lab = ptr; break;
            default: break;
        }
    }
    if (!p8 || !p16 || !p32 || !lab) {   // fall back to metadata order
        p8 = (const float*)d_in[0]; p16 = (const float*)d_in[1];
        p32 = (const float*)d_in[2]; lab = (const float*)d_in[3];
    }

    dim3 blk(256);
    dim3 gA((AT + 255) / 256, BB);
    k_zero<<<1, 32>>>();
    k_decode<<<gA, blk>>>(p8, p16, p32, lab);
    k_cost<<<dim3((AT + 255) / 256, GG, BB), blk>>>(lab);
    k_select<<<dim3(GG, BB), 256>>>();
    k_loss<<<gA, blk>>>(p8, p16, p32, lab);
    k_final<<<1, 1>>>((float*)d_out);
}